// round 11
// baseline (speedup 1.0000x reference)
#include <cuda_runtime.h>
#include <cuda_fp16.h>

// out[i, :] = sum_k ppr_scores[i,k] * x[ppr_idx[i,k], :]
// N=100000, K=32, D=128 (fp32 in/out, 1e-3 rel-err budget).
// Two-pass: (1) convert x -> fp16 scratch (~12us, HBM floor);
// (2) gather 256B fp16 rows with half-warp row pairing, fp32 accumulate.
//
// R11: R9 body (scalar FMA — FFMA2 was a wash) with the in-flight load
// batch widened 2 -> 4 LDG.128 per iteration. R10 profile showed no pipe
// saturated (L1 77, L2 66, fma 46, issue 54) => latency-bound; more MLP
// per warp (192 vs 112 outstanding gathers/SM) should buy back L2 feed
// even at the cost of some occupancy (regs ~40, occ ~75-80%).

#define KNEIGH 32
#define DFEAT  128
#define NMAX   100000

// fp16 copy of x: 100000 * 128 * 2B = 25.6 MB (L2-resident).
__device__ __align__(16) static __half g_xh[(size_t)NMAX * DFEAT];

// ---------------- pass 1: fp32 -> fp16 convert ----------------
__global__ __launch_bounds__(256) void cvt_kernel(
    const float4* __restrict__ x, int n8)
{
    const int i = blockIdx.x * blockDim.x + threadIdx.x;
    if (i >= n8) return;

    const float4 a = x[2 * i];
    const float4 b = x[2 * i + 1];

    __half2 h0 = __floats2half2_rn(a.x, a.y);
    __half2 h1 = __floats2half2_rn(a.z, a.w);
    __half2 h2 = __floats2half2_rn(b.x, b.y);
    __half2 h3 = __floats2half2_rn(b.z, b.w);

    uint4 p;
    p.x = *reinterpret_cast<unsigned*>(&h0);
    p.y = *reinterpret_cast<unsigned*>(&h1);
    p.z = *reinterpret_cast<unsigned*>(&h2);
    p.w = *reinterpret_cast<unsigned*>(&h3);
    reinterpret_cast<uint4*>(g_xh)[i] = p;
}

// ---------------- pass 2: gather-reduce ----------------
// One warp per output row. Half-warp row pairing: one LDG.128 covers two
// neighbor rows (lanes 0-15 -> row 2u, lanes 16-31 -> row 2u+1; uint4 = 8
// features/lane). Even/odd-k partials folded by shfl_xor(16) at the end.
__global__ __launch_bounds__(256) void ppr_gather_kernel(
    const int*   __restrict__ idx,    // [N, 32]
    const float* __restrict__ sc,     // [N, 32]
    float4*      __restrict__ out,    // [N, 32] float4
    int n)
{
    const int warp = (blockIdx.x * blockDim.x + threadIdx.x) >> 5;
    const int lane = threadIdx.x & 31;
    if (warp >= n) return;

    const int half_id = lane >> 4;        // 0: even-k rows, 1: odd-k rows
    const int fbase16 = lane & 15;        // 16B-chunk index within a row

    const int   my_j = idx[warp * KNEIGH + lane];
    const float my_s = sc[warp * KNEIGH + lane];

    float a0 = 0.f, a1 = 0.f, a2 = 0.f, a3 = 0.f;
    float a4 = 0.f, a5 = 0.f, a6 = 0.f, a7 = 0.f;

    #pragma unroll
    for (int i = 0; i < KNEIGH / 2; i += 4) {
        // 4 row-pair LDG.128 in flight (8 neighbor rows per trip).
        int   j[4];
        float s[4];
        uint4 v[4];
        #pragma unroll
        for (int u = 0; u < 4; ++u) {
            j[u] = __shfl_sync(0xffffffffu, my_j, 2 * (i + u) + half_id);
            s[u] = __shfl_sync(0xffffffffu, my_s, 2 * (i + u) + half_id);
        }
        #pragma unroll
        for (int u = 0; u < 4; ++u) {
            v[u] = reinterpret_cast<const uint4*>(
                       g_xh + (size_t)j[u] * DFEAT)[fbase16];
        }
        #pragma unroll
        for (int u = 0; u < 4; ++u) {
            const float2 f0 = __half22float2(*reinterpret_cast<const __half2*>(&v[u].x));
            const float2 f1 = __half22float2(*reinterpret_cast<const __half2*>(&v[u].y));
            const float2 f2 = __half22float2(*reinterpret_cast<const __half2*>(&v[u].z));
            const float2 f3 = __half22float2(*reinterpret_cast<const __half2*>(&v[u].w));
            a0 += s[u] * f0.x;  a1 += s[u] * f0.y;
            a2 += s[u] * f1.x;  a3 += s[u] * f1.y;
            a4 += s[u] * f2.x;  a5 += s[u] * f2.y;
            a6 += s[u] * f3.x;  a7 += s[u] * f3.y;
        }
    }

    // Fold even-k (lanes 0-15) and odd-k (lanes 16-31) partial sums.
    a0 += __shfl_xor_sync(0xffffffffu, a0, 16);
    a1 += __shfl_xor_sync(0xffffffffu, a1, 16);
    a2 += __shfl_xor_sync(0xffffffffu, a2, 16);
    a3 += __shfl_xor_sync(0xffffffffu, a3, 16);
    a4 += __shfl_xor_sync(0xffffffffu, a4, 16);
    a5 += __shfl_xor_sync(0xffffffffu, a5, 16);
    a6 += __shfl_xor_sync(0xffffffffu, a6, 16);
    a7 += __shfl_xor_sync(0xffffffffu, a7, 16);

    const float4 r = half_id ? make_float4(a4, a5, a6, a7)
                             : make_float4(a0, a1, a2, a3);
    out[warp * (DFEAT / 4) + fbase16 * 2 + half_id] = r;
}

extern "C" void kernel_launch(void* const* d_in, const int* in_sizes, int n_in,
                              void* d_out, int out_size)
{
    const float4* x   = (const float4*)d_in[0];   // [N, D] fp32
    const int*    idx = (const int*)d_in[1];      // [N, K] int32
    const float*  sc  = (const float*)d_in[2];    // [N, K] fp32
    float4*       out = (float4*)d_out;           // [N, D] fp32

    const int n  = in_sizes[1] / KNEIGH;          // N rows
    const int n8 = in_sizes[0] / 8;               // convert units (8 floats)

    cvt_kernel<<<(n8 + 255) / 256, 256>>>(x, n8);

    const int warps_per_block = 8;                // 256 threads
    const int blocks = (n + warps_per_block - 1) / warps_per_block;
    ppr_gather_kernel<<<blocks, warps_per_block * 32>>>(idx, sc, out, n);
}

// round 12
// speedup vs baseline: 1.0372x; 1.0372x over previous
#include <cuda_runtime.h>
#include <cuda_fp16.h>

// out[i, :] = sum_k ppr_scores[i,k] * x[ppr_idx[i,k], :]
// N=100000, K=32, D=128 (fp32 in/out, 1e-3 rel-err budget).
// Two-pass: (1) convert x -> fp16 scratch; (2) gather 256B fp16 rows with
// half-warp row pairing, fp32 accumulate, shfl_xor(16) fold.
//
// R12:
//  - gather: software-pipelined (prefetch next row-pair's shfl+LDG before
//    consuming current) so loads stay in flight without relying on ptxas
//    batching (R11 showed it clamps to 32 regs and serializes).
//  - cvt: __ldcs streaming reads of x — x is dead after conversion; don't
//    let it evict the hot 25.6MB x_half from L2 across graph replays.

#define KNEIGH 32
#define DFEAT  128
#define NMAX   100000

__device__ __align__(16) static __half g_xh[(size_t)NMAX * DFEAT];

// ---------------- pass 1: fp32 -> fp16 convert ----------------
__global__ __launch_bounds__(256) void cvt_kernel(
    const float4* __restrict__ x, int n8)
{
    const int i = blockIdx.x * blockDim.x + threadIdx.x;
    if (i >= n8) return;

    const float4 a = __ldcs(&x[2 * i]);        // streaming: evict-first
    const float4 b = __ldcs(&x[2 * i + 1]);

    __half2 h0 = __floats2half2_rn(a.x, a.y);
    __half2 h1 = __floats2half2_rn(a.z, a.w);
    __half2 h2 = __floats2half2_rn(b.x, b.y);
    __half2 h3 = __floats2half2_rn(b.z, b.w);

    uint4 p;
    p.x = *reinterpret_cast<unsigned*>(&h0);
    p.y = *reinterpret_cast<unsigned*>(&h1);
    p.z = *reinterpret_cast<unsigned*>(&h2);
    p.w = *reinterpret_cast<unsigned*>(&h3);
    reinterpret_cast<uint4*>(g_xh)[i] = p;
}

// ---------------- pass 2: gather-reduce ----------------
// One warp per output row; one LDG.128 covers two neighbor rows
// (lanes 0-15 -> row 2u, lanes 16-31 -> row 2u+1; uint4 = 8 features/lane).
__global__ __launch_bounds__(256) void ppr_gather_kernel(
    const int*   __restrict__ idx,    // [N, 32]
    const float* __restrict__ sc,     // [N, 32]
    float4*      __restrict__ out,    // [N, 32] float4
    int n)
{
    const int warp = (blockIdx.x * blockDim.x + threadIdx.x) >> 5;
    const int lane = threadIdx.x & 31;
    if (warp >= n) return;

    const int half_id = lane >> 4;
    const int fbase16 = lane & 15;

    const int   my_j = idx[warp * KNEIGH + lane];
    const float my_s = sc[warp * KNEIGH + lane];

    float a0 = 0.f, a1 = 0.f, a2 = 0.f, a3 = 0.f;
    float a4 = 0.f, a5 = 0.f, a6 = 0.f, a7 = 0.f;

    // ---- software pipeline: stage 0 prefetch (row-pairs 0 and 1) ----
    int   jA = __shfl_sync(0xffffffffu, my_j, half_id);
    float sA = __shfl_sync(0xffffffffu, my_s, half_id);
    int   jB = __shfl_sync(0xffffffffu, my_j, 2 + half_id);
    float sB = __shfl_sync(0xffffffffu, my_s, 2 + half_id);
    uint4 vA = reinterpret_cast<const uint4*>(g_xh + (size_t)jA * DFEAT)[fbase16];
    uint4 vB = reinterpret_cast<const uint4*>(g_xh + (size_t)jB * DFEAT)[fbase16];

    #pragma unroll
    for (int i = 0; i < KNEIGH / 2; i += 2) {
        // Prefetch next pair of row-pairs before consuming current.
        uint4 nA, nB;
        float nsA = 0.f, nsB = 0.f;
        if (i + 2 < KNEIGH / 2) {
            const int njA = __shfl_sync(0xffffffffu, my_j, 2 * (i + 2) + half_id);
            nsA           = __shfl_sync(0xffffffffu, my_s, 2 * (i + 2) + half_id);
            const int njB = __shfl_sync(0xffffffffu, my_j, 2 * (i + 3) + half_id);
            nsB           = __shfl_sync(0xffffffffu, my_s, 2 * (i + 3) + half_id);
            nA = reinterpret_cast<const uint4*>(g_xh + (size_t)njA * DFEAT)[fbase16];
            nB = reinterpret_cast<const uint4*>(g_xh + (size_t)njB * DFEAT)[fbase16];
        }

        // Consume current two row-pairs.
        {
            const float2 f0 = __half22float2(*reinterpret_cast<const __half2*>(&vA.x));
            const float2 f1 = __half22float2(*reinterpret_cast<const __half2*>(&vA.y));
            const float2 f2 = __half22float2(*reinterpret_cast<const __half2*>(&vA.z));
            const float2 f3 = __half22float2(*reinterpret_cast<const __half2*>(&vA.w));
            a0 += sA * f0.x;  a1 += sA * f0.y;
            a2 += sA * f1.x;  a3 += sA * f1.y;
            a4 += sA * f2.x;  a5 += sA * f2.y;
            a6 += sA * f3.x;  a7 += sA * f3.y;
        }
        {
            const float2 f0 = __half22float2(*reinterpret_cast<const __half2*>(&vB.x));
            const float2 f1 = __half22float2(*reinterpret_cast<const __half2*>(&vB.y));
            const float2 f2 = __half22float2(*reinterpret_cast<const __half2*>(&vB.z));
            const float2 f3 = __half22float2(*reinterpret_cast<const __half2*>(&vB.w));
            a0 += sB * f0.x;  a1 += sB * f0.y;
            a2 += sB * f1.x;  a3 += sB * f1.y;
            a4 += sB * f2.x;  a5 += sB * f2.y;
            a6 += sB * f3.x;  a7 += sB * f3.y;
        }

        vA = nA;  sA = nsA;
        vB = nB;  sB = nsB;
    }

    a0 += __shfl_xor_sync(0xffffffffu, a0, 16);
    a1 += __shfl_xor_sync(0xffffffffu, a1, 16);
    a2 += __shfl_xor_sync(0xffffffffu, a2, 16);
    a3 += __shfl_xor_sync(0xffffffffu, a3, 16);
    a4 += __shfl_xor_sync(0xffffffffu, a4, 16);
    a5 += __shfl_xor_sync(0xffffffffu, a5, 16);
    a6 += __shfl_xor_sync(0xffffffffu, a6, 16);
    a7 += __shfl_xor_sync(0xffffffffu, a7, 16);

    const float4 r = half_id ? make_float4(a4, a5, a6, a7)
                             : make_float4(a0, a1, a2, a3);
    out[warp * (DFEAT / 4) + fbase16 * 2 + half_id] = r;
}

extern "C" void kernel_launch(void* const* d_in, const int* in_sizes, int n_in,
                              void* d_out, int out_size)
{
    const float4* x   = (const float4*)d_in[0];
    const int*    idx = (const int*)d_in[1];
    const float*  sc  = (const float*)d_in[2];
    float4*       out = (float4*)d_out;

    const int n  = in_sizes[1] / KNEIGH;
    const int n8 = in_sizes[0] / 8;

    cvt_kernel<<<(n8 + 255) / 256, 256>>>(x, n8);

    const int warps_per_block = 8;
    const int blocks = (n + warps_per_block - 1) / warps_per_block;
    ppr_gather_kernel<<<blocks, warps_per_block * 32>>>(idx, sc, out, n);
}